// round 1
// baseline (speedup 1.0000x reference)
#include <cuda_runtime.h>
#include <math.h>

#define Bn 32
#define Nn 1024
#define Fn 128
#define Dn 128

// dk = (D^-0.5)/N = 1/(sqrt(128)*1024)
#define DKC 8.6316745750311e-05f

// ---------------- scratch (device globals; no allocation allowed) ----------------
__device__ float g_M[Fn * Fn];       // M[f][g] = sum_d Wq[f,d]*Wk[g,d]
__device__ float g_u12[Fn];          // u12[f] = sum_d Wq[f,d]*bk[d] + Wk[f,d]*bq[d]
__device__ float g_c[1];             // bq . bk
__device__ float g_A[Bn * Fn];       // A_b = sum_i aq[b,i,:]
__device__ float g_wcomb[Bn * Fn];   // Wq@S_b - u12
__device__ float g_ccomb[Bn];        // bq.S_b - c
__device__ float g_agg[Bn * Nn];     // agg, later exp values
__device__ float g_nrm2[Bn];
__device__ float g_Z[Bn];
__device__ float g_u[Bn * Fn];       // sum_i w_i * aq_i
__device__ float g_sw[Bn];           // sum_i w_i

// ---------------- K_init: zero atomic accumulators (graph-replayed!) ----------------
__global__ void k_init() {
    int t = blockIdx.x * blockDim.x + threadIdx.x;
    int nt = gridDim.x * blockDim.x;
    for (int i = t; i < Bn * Fn; i += nt) { g_A[i] = 0.f; g_u[i] = 0.f; }
    if (t < Bn) { g_nrm2[t] = 0.f; g_sw[t] = 0.f; }
}

// ---------------- K0: M = Wq Wk^T, u12, c ----------------
__global__ void k0_precompute(const float* __restrict__ Wq, const float* __restrict__ Wk,
                              const float* __restrict__ bq, const float* __restrict__ bk) {
    __shared__ float srow[Fn];
    int blk = blockIdx.x;
    int t = threadIdx.x;
    if (blk < Fn) {
        // block f computes M[f][:]
        srow[t] = Wq[blk * Fn + t];
        __syncthreads();
        float acc = 0.f;
        #pragma unroll 4
        for (int d = 0; d < Fn; d++) acc = fmaf(srow[d], Wk[t * Fn + d], acc);
        g_M[blk * Fn + t] = acc;
    } else {
        // block 128: u12 and c
        __shared__ float sbq[Fn];
        __shared__ float sbk[Fn];
        sbq[t] = bq[t];
        sbk[t] = bk[t];
        __syncthreads();
        float acc = 0.f;
        #pragma unroll 4
        for (int d = 0; d < Fn; d++) {
            acc = fmaf(Wq[t * Fn + d], sbk[d], acc);
            acc = fmaf(Wk[t * Fn + d], sbq[d], acc);
        }
        g_u12[t] = acc;
        if (t == 0) {
            float c = 0.f;
            for (int d = 0; d < Fn; d++) c = fmaf(sbq[d], sbk[d], c);
            g_c[0] = c;
        }
    }
}

// ---------------- K1: A_b = sum_i aq[b,i,:] ----------------
__global__ void k1_colsum(const float* __restrict__ aq) {
    int b = blockIdx.y;
    int i0 = blockIdx.x * 128;                // 8 chunks of 128 rows
    int f = threadIdx.x;
    const float* p = aq + ((size_t)(b * Nn + i0)) * Fn + f;
    float acc = 0.f;
    #pragma unroll 8
    for (int r = 0; r < 128; r++) acc += p[r * Fn];
    atomicAdd(&g_A[b * Fn + f], acc);
}

// ---------------- K2: per-batch S, wcomb, ccomb ----------------
__global__ void k2_batchvec(const float* __restrict__ Wq, const float* __restrict__ Wk,
                            const float* __restrict__ bq, const float* __restrict__ bk) {
    __shared__ float S[Dn];
    __shared__ float red[Fn];
    int b = blockIdx.x;
    int t = threadIdx.x;
    // S[d] = sum_f Wk[f,d]*A[f] + N*bk[d]
    float s = 1024.0f * bk[t];
    #pragma unroll 4
    for (int f = 0; f < Fn; f++) s = fmaf(Wk[f * Fn + t], g_A[b * Fn + f], s);
    S[t] = s;
    __syncthreads();
    // wcomb[f] = sum_d Wq[f,d]*S[d] - u12[f]
    float w = -g_u12[t];
    #pragma unroll 4
    for (int d = 0; d < Dn; d++) w = fmaf(Wq[t * Fn + d], S[d], w);
    g_wcomb[b * Fn + t] = w;
    // ccomb = sum_d bq[d]*S[d] - c
    red[t] = bq[t] * S[t];
    __syncthreads();
    for (int off = 64; off > 0; off >>= 1) {
        if (t < off) red[t] += red[t + off];
        __syncthreads();
    }
    if (t == 0) g_ccomb[b] = red[0] - g_c[0];
}

// ---------------- K3: per-atom agg (dominant kernel) ----------------
// block = 256 threads (8 warps), 64 atoms/block, 8 atoms per lane.
// smem: M padded to 129 floats/row (conflict-free), X padded to 132 (16B-aligned rows).
#define SM_M_STRIDE 129
#define SM_X_STRIDE 132
#define K3_SMEM ((Fn * SM_M_STRIDE + 64 * SM_X_STRIDE) * 4)

__global__ void __launch_bounds__(256, 2) k3_agg(const float* __restrict__ aq,
                                                 const float* __restrict__ mask) {
    extern __shared__ float sm[];
    float* sM = sm;                       // [128][129]
    float* sX = sm + Fn * SM_M_STRIDE;    // [64][132]
    const int b = blockIdx.y;
    const int atom0 = blockIdx.x * 64;

    for (int idx = threadIdx.x; idx < Fn * Fn; idx += 256)
        sM[(idx >> 7) * SM_M_STRIDE + (idx & 127)] = g_M[idx];
    const float* aqb = aq + ((size_t)(b * Nn + atom0)) * Fn;
    for (int idx = threadIdx.x; idx < 64 * Fn; idx += 256)
        sX[(idx >> 7) * SM_X_STRIDE + (idx & 127)] = aqb[idx];
    __syncthreads();

    const int warp = threadIdx.x >> 5;
    const int lane = threadIdx.x & 31;
    const int r0 = warp * 8;

    float acc[4][8];
    #pragma unroll
    for (int k = 0; k < 4; k++)
        #pragma unroll
        for (int a = 0; a < 8; a++) acc[k][a] = 0.f;

    // y_f^a = sum_g M[f,g] x^a_g  for f = lane+32k
    #pragma unroll 1
    for (int g = 0; g < Fn; g += 4) {
        float4 xg[8];
        #pragma unroll
        for (int a = 0; a < 8; a++)
            xg[a] = *reinterpret_cast<const float4*>(&sX[(r0 + a) * SM_X_STRIDE + g]);
        #pragma unroll
        for (int k = 0; k < 4; k++) {
            const float* mrow = &sM[(lane + 32 * k) * SM_M_STRIDE + g];
            const float m0 = mrow[0], m1 = mrow[1], m2 = mrow[2], m3 = mrow[3];
            #pragma unroll
            for (int a = 0; a < 8; a++) {
                float v = acc[k][a];
                v = fmaf(m0, xg[a].x, v);
                v = fmaf(m1, xg[a].y, v);
                v = fmaf(m2, xg[a].z, v);
                v = fmaf(m3, xg[a].w, v);
                acc[k][a] = v;
            }
        }
    }

    // epilogue: p1 = x.Mx (quadratic form), p2 = x.wcomb
    const float* wcb = &g_wcomb[b * Fn];
    float wc[4];
    #pragma unroll
    for (int k = 0; k < 4; k++) wc[k] = wcb[lane + 32 * k];
    const float ccomb = g_ccomb[b];

    #pragma unroll
    for (int a = 0; a < 8; a++) {
        float p1 = 0.f, p2 = 0.f;
        #pragma unroll
        for (int k = 0; k < 4; k++) {
            float xf = sX[(r0 + a) * SM_X_STRIDE + lane + 32 * k];
            p1 = fmaf(xf, acc[k][a], p1);
            p2 = fmaf(xf, wc[k], p2);
        }
        #pragma unroll
        for (int off = 16; off > 0; off >>= 1) {
            p1 += __shfl_xor_sync(0xffffffffu, p1, off);
            p2 += __shfl_xor_sync(0xffffffffu, p2, off);
        }
        if (lane == 0) {
            int i = atom0 + r0 + a;
            float mv = mask[b * Nn + i];
            float aggv = mv * DKC * (p2 + ccomb - p1);
            g_agg[b * Nn + i] = aggv;
            atomicAdd(&g_nrm2[b], aggv * aggv);
        }
    }
}

// ---------------- K4: normalize + exp + softmax denominator ----------------
__global__ void k4_softmax_denom(const float* __restrict__ mask) {
    __shared__ float red[256];
    int b = blockIdx.x;
    int t = threadIdx.x;
    float invn = 1.0f / sqrtf(g_nrm2[b]);
    float local = 0.f;
    for (int i = t; i < Nn; i += 256) {
        float a = g_agg[b * Nn + i];
        float mv = mask[b * Nn + i];
        float e = (mv != 0.f) ? expf(a * invn) : 0.f;   // masked: agg/nrm - 1e9 -> exp == 0
        g_agg[b * Nn + i] = e;
        local += e;
    }
    red[t] = local;
    __syncthreads();
    for (int off = 128; off > 0; off >>= 1) {
        if (t < off) red[t] += red[t + off];
        __syncthreads();
    }
    if (t == 0) g_Z[b] = red[0];
}

// ---------------- K5: attn out + weighted atom sum ----------------
__global__ void k5_attn_wsum(const float* __restrict__ aq, const float* __restrict__ mask,
                             float* __restrict__ attn_out) {
    __shared__ float w[128];
    int b = blockIdx.y;
    int i0 = blockIdx.x * 128;
    int t = threadIdx.x;
    int i = i0 + t;
    float Z = g_Z[b];
    float attn = g_agg[b * Nn + i] / Z;
    if (attn_out) attn_out[b * Nn + i] = attn;
    float wv = mask[b * Nn + i] * attn;
    w[t] = wv;
    __syncthreads();
    // u[f] += sum_a w[a] * aq[b, i0+a, f]
    float acc = 0.f;
    const float* p = aq + ((size_t)(b * Nn + i0)) * Fn + t;
    #pragma unroll 8
    for (int a = 0; a < 128; a++) acc = fmaf(w[a], p[a * Fn], acc);
    atomicAdd(&g_u[b * Fn + t], acc);
    if (t == 0) {
        float s = 0.f;
        for (int a = 0; a < 128; a++) s += w[a];
        atomicAdd(&g_sw[b], s);
    }
}

// ---------------- K6: context = u @ Wv + sw * bv ----------------
__global__ void k6_context(const float* __restrict__ Wv, const float* __restrict__ bv,
                           float* __restrict__ ctx_out) {
    if (!ctx_out) return;
    int b = blockIdx.x;
    int d = threadIdx.x;
    float ctx = g_sw[b] * bv[d];
    #pragma unroll 4
    for (int f = 0; f < Fn; f++) ctx = fmaf(Wv[f * Fn + d], g_u[b * Fn + f], ctx);
    ctx_out[b * Dn + d] = ctx;
}

// ---------------- host launch ----------------
extern "C" void kernel_launch(void* const* d_in, const int* in_sizes, int n_in,
                              void* d_out, int out_size) {
    const float* aq   = (const float*)d_in[0];
    const float* mask = (const float*)d_in[1];
    const float* Wq   = (const float*)d_in[2];
    const float* bq   = (const float*)d_in[3];
    const float* Wk   = (const float*)d_in[4];
    const float* bk   = (const float*)d_in[5];
    const float* Wv   = (const float*)d_in[6];
    const float* bv   = (const float*)d_in[7];

    float* out = (float*)d_out;
    float* attn_out = nullptr;
    float* ctx_out = nullptr;
    if (out_size >= Bn * Nn + Bn * Dn) { attn_out = out; ctx_out = out + Bn * Nn; }
    else if (out_size == Bn * Nn)      { attn_out = out; }
    else                               { ctx_out = out; }

    cudaFuncSetAttribute(k3_agg, cudaFuncAttributeMaxDynamicSharedMemorySize, K3_SMEM);

    k_init<<<16, 256>>>();
    k0_precompute<<<Fn + 1, 128>>>(Wq, Wk, bq, bk);
    k1_colsum<<<dim3(8, Bn), 128>>>(aq);
    k2_batchvec<<<Bn, 128>>>(Wq, Wk, bq, bk);
    k3_agg<<<dim3(16, Bn), 256, K3_SMEM>>>(aq, mask);
    k4_softmax_denom<<<Bn, 256>>>(mask);
    k5_attn_wsum<<<dim3(8, Bn), 128>>>(aq, mask, attn_out);
    k6_context<<<Bn, 128>>>(Wv, bv, ctx_out);
}

// round 2
// speedup vs baseline: 1.2155x; 1.2155x over previous
#include <cuda_runtime.h>
#include <math.h>

#define Bn 32
#define Nn 1024
#define Fn 128
#define Dn 128

// dk = (D^-0.5)/N = 1/(sqrt(128)*1024)
#define DKC 8.6316745750311e-05f

typedef unsigned long long ull;

// ---------------- scratch (device globals) ----------------
__device__ float g_M[Fn * Fn];            // M[f][g] = sum_d Wq[f,d]*Wk[g,d]
__device__ float g_u12[Fn];               // Wq bk + Wk bq
__device__ float g_c[1];                  // bq . bk
__device__ float g_Apart[Bn][8][Fn];      // partial column sums of aq
__device__ float g_agg[Bn * Nn];          // agg, then exp values (in-place)
__device__ float g_n2part[Bn][16];        // per-block partial sum of agg^2
__device__ float g_Z[Bn];                 // softmax denominator
__device__ float g_upart[Bn][8][Fn];      // partial sum_i w_i aq_i
__device__ float g_swpart[Bn][8];         // partial sum_i w_i

// ---------------- f32x2 helpers ----------------
__device__ __forceinline__ void ffma2(ull& d, ull a, ull b) {
    asm("fma.rn.f32x2 %0, %1, %2, %0;" : "+l"(d) : "l"(a), "l"(b));
}
__device__ __forceinline__ ull pk2(float lo, float hi) {
    ull r; asm("mov.b64 %0, {%1,%2};" : "=l"(r) : "f"(lo), "f"(hi)); return r;
}
__device__ __forceinline__ void upk2(ull v, float& lo, float& hi) {
    asm("mov.b64 {%0,%1}, %2;" : "=f"(lo), "=f"(hi) : "l"(v));
}

// ============ kA: fused precompute (M, u12, c) + column-sum partials ============
__global__ void kA(const float* __restrict__ aq,
                   const float* __restrict__ Wq, const float* __restrict__ Wk,
                   const float* __restrict__ bq, const float* __restrict__ bk) {
    __shared__ float srow[Fn];
    int blk = blockIdx.x;
    int t = threadIdx.x;
    if (blk < Fn) {
        // M row blk
        srow[t] = Wq[blk * Fn + t];
        __syncthreads();
        float a0 = 0.f, a1 = 0.f, a2 = 0.f, a3 = 0.f;
        #pragma unroll 8
        for (int d = 0; d < Fn; d += 4) {
            a0 = fmaf(srow[d + 0], Wk[t * Fn + d + 0], a0);
            a1 = fmaf(srow[d + 1], Wk[t * Fn + d + 1], a1);
            a2 = fmaf(srow[d + 2], Wk[t * Fn + d + 2], a2);
            a3 = fmaf(srow[d + 3], Wk[t * Fn + d + 3], a3);
        }
        g_M[blk * Fn + t] = (a0 + a1) + (a2 + a3);
    } else if (blk == Fn) {
        __shared__ float sbq[Fn], sbk[Fn];
        sbq[t] = bq[t]; sbk[t] = bk[t];
        __syncthreads();
        float a0 = 0.f, a1 = 0.f;
        #pragma unroll 8
        for (int d = 0; d < Fn; d += 2) {
            a0 = fmaf(Wq[t * Fn + d], sbk[d], a0);
            a0 = fmaf(Wk[t * Fn + d], sbq[d], a0);
            a1 = fmaf(Wq[t * Fn + d + 1], sbk[d + 1], a1);
            a1 = fmaf(Wk[t * Fn + d + 1], sbq[d + 1], a1);
        }
        g_u12[t] = a0 + a1;
        if (t == 0) {
            float c = 0.f;
            for (int d = 0; d < Fn; d++) c = fmaf(sbq[d], sbk[d], c);
            g_c[0] = c;
        }
    } else {
        // column-sum partial: block m handles 128 rows of batch b
        int m = blk - (Fn + 1);
        int b = m >> 3, c = m & 7;
        const float* p = aq + ((size_t)(b * Nn + c * 128)) * Fn + t;
        float a0 = 0.f, a1 = 0.f, a2 = 0.f, a3 = 0.f;
        #pragma unroll 8
        for (int r = 0; r < 128; r += 4) {
            a0 += p[(r + 0) * Fn];
            a1 += p[(r + 1) * Fn];
            a2 += p[(r + 2) * Fn];
            a3 += p[(r + 3) * Fn];
        }
        g_Apart[b][c][t] = (a0 + a1) + (a2 + a3);
    }
}

// ============ kB: dominant kernel — per-atom agg via packed FFMA2 ============
// 64 atoms/block, 256 threads (8 warps x 8 atoms). Prologue recomputes
// S_b, wcomb, ccomb per block (replaces the old 27.9us k2 kernel).
#define STM 129                         // M row stride (conflict-free)
#define STX 66                          // transposed X stride (even, 2-way max)
#define KB_SMEM ((Fn * STM + Fn * STX + 3 * Fn) * 4)

__global__ void __launch_bounds__(256, 2) kB(const float* __restrict__ aq,
                                             const float* __restrict__ mask,
                                             const float* __restrict__ Wq,
                                             const float* __restrict__ Wk,
                                             const float* __restrict__ bq,
                                             const float* __restrict__ bk) {
    extern __shared__ float sm[];
    float* sM  = sm;                     // [128][129]
    float* sXT = sM + Fn * STM;          // [128 f][66] -> sXT[f*STX + atom]
    float* sA  = sXT + Fn * STX;         // [128]
    float* sS  = sA + Fn;                // [128]
    float* sWc = sS + Fn;                // [128]
    __shared__ float sred[8];

    const int b = blockIdx.y;
    const int atom0 = blockIdx.x * 64;
    const int t = threadIdx.x;
    const int warp = t >> 5, lane = t & 31;
    const int r0 = warp * 8;

    // --- load M and transposed X into smem ---
    for (int idx = t; idx < Fn * Fn; idx += 256)
        sM[(idx >> 7) * STM + (idx & 127)] = g_M[idx];
    const float* aqb = aq + ((size_t)(b * Nn + atom0)) * Fn;
    for (int idx = t; idx < 64 * Fn; idx += 256)
        sXT[(idx & 127) * STX + (idx >> 7)] = aqb[idx];

    // --- prologue: A, then S = Wk^T A + N*bk, then wcomb = Wq S - u12, ccomb ---
    if (t < Fn) {
        float s = 0.f;
        #pragma unroll
        for (int c = 0; c < 8; c++) s += g_Apart[b][c][t];
        sA[t] = s;
    }
    __syncthreads();   // sA ready; also M/X smem stores done

    if (t < Fn) {
        float s0 = 1024.0f * bk[t], s1 = 0.f, s2 = 0.f, s3 = 0.f;
        #pragma unroll 8
        for (int f = 0; f < Fn; f += 4) {
            s0 = fmaf(Wk[(f + 0) * Fn + t], sA[f + 0], s0);
            s1 = fmaf(Wk[(f + 1) * Fn + t], sA[f + 1], s1);
            s2 = fmaf(Wk[(f + 2) * Fn + t], sA[f + 2], s2);
            s3 = fmaf(Wk[(f + 3) * Fn + t], sA[f + 3], s3);
        }
        sS[t] = (s0 + s1) + (s2 + s3);
    }
    __syncthreads();

    float cc_part = 0.f;
    if (t < Fn) {
        float w0 = -g_u12[t], w1 = 0.f, w2 = 0.f, w3 = 0.f;
        const float* wq = Wq + t * Fn;
        #pragma unroll 8
        for (int d = 0; d < Fn; d += 4) {
            w0 = fmaf(wq[d + 0], sS[d + 0], w0);
            w1 = fmaf(wq[d + 1], sS[d + 1], w1);
            w2 = fmaf(wq[d + 2], sS[d + 2], w2);
            w3 = fmaf(wq[d + 3], sS[d + 3], w3);
        }
        sWc[t] = (w0 + w1) + (w2 + w3);
        cc_part = bq[t] * sS[t];
    }
    // reduce ccomb
    #pragma unroll
    for (int off = 16; off > 0; off >>= 1)
        cc_part += __shfl_xor_sync(0xffffffffu, cc_part, off);
    if (lane == 0) sred[warp] = cc_part;
    __syncthreads();
    const float ccomb = (sred[0] + sred[1] + sred[2] + sred[3]) - g_c[0];
    __syncthreads();   // protect sred reuse below

    // --- main loop: y^a_f = sum_g M[f,g] x^a_g, packed over atom pairs ---
    ull acc[4][4];
    #pragma unroll
    for (int k = 0; k < 4; k++)
        #pragma unroll
        for (int a2 = 0; a2 < 4; a2++) acc[k][a2] = 0ull;

    #pragma unroll 4
    for (int g = 0; g < Fn; g++) {
        const float* xp = &sXT[g * STX + r0];
        ull x0 = *reinterpret_cast<const ull*>(xp + 0);
        ull x1 = *reinterpret_cast<const ull*>(xp + 2);
        ull x2 = *reinterpret_cast<const ull*>(xp + 4);
        ull x3 = *reinterpret_cast<const ull*>(xp + 6);
        #pragma unroll
        for (int k = 0; k < 4; k++) {
            float m = sM[(lane + 32 * k) * STM + g];
            ull mm = pk2(m, m);
            ffma2(acc[k][0], mm, x0);
            ffma2(acc[k][1], mm, x1);
            ffma2(acc[k][2], mm, x2);
            ffma2(acc[k][3], mm, x3);
        }
    }

    // --- epilogue: p1 = x.Mx, p2 = x.wcomb per atom ---
    float wc[4];
    #pragma unroll
    for (int k = 0; k < 4; k++) wc[k] = sWc[lane + 32 * k];

    float n2local = 0.f;
    #pragma unroll
    for (int a2 = 0; a2 < 4; a2++) {
        float ylo[4], yhi[4];
        #pragma unroll
        for (int k = 0; k < 4; k++) upk2(acc[k][a2], ylo[k], yhi[k]);
        #pragma unroll
        for (int half = 0; half < 2; half++) {
            int a = 2 * a2 + half;
            float p1 = 0.f, p2 = 0.f;
            #pragma unroll
            for (int k = 0; k < 4; k++) {
                float xf = sXT[(lane + 32 * k) * STX + r0 + a];
                p1 = fmaf(xf, half ? yhi[k] : ylo[k], p1);
                p2 = fmaf(xf, wc[k], p2);
            }
            #pragma unroll
            for (int off = 16; off > 0; off >>= 1) {
                p1 += __shfl_xor_sync(0xffffffffu, p1, off);
                p2 += __shfl_xor_sync(0xffffffffu, p2, off);
            }
            if (lane == 0) {
                int i = atom0 + r0 + a;
                float mv = mask[b * Nn + i];
                float aggv = mv * DKC * (p2 + ccomb - p1);
                g_agg[b * Nn + i] = aggv;
                n2local = fmaf(aggv, aggv, n2local);
            }
        }
    }
    if (lane == 0) sred[warp] = n2local;
    __syncthreads();
    if (t == 0) {
        float s = 0.f;
        #pragma unroll
        for (int w = 0; w < 8; w++) s += sred[w];
        g_n2part[b][blockIdx.x] = s;
    }
}

// ============ kC: normalize + exp + softmax denominator ============
__global__ void kC(const float* __restrict__ mask) {
    __shared__ float red[256];
    int b = blockIdx.x;
    int t = threadIdx.x;
    float n2 = 0.f;
    #pragma unroll
    for (int j = 0; j < 16; j++) n2 += g_n2part[b][j];
    float invn = rsqrtf(n2);
    float local = 0.f;
    #pragma unroll
    for (int i = t; i < Nn; i += 256) {
        float a = g_agg[b * Nn + i];
        float mv = mask[b * Nn + i];
        float e = (mv != 0.f) ? expf(a * invn) : 0.f;  // masked -> -1e9 -> exp 0
        g_agg[b * Nn + i] = e;
        local += e;
    }
    red[t] = local;
    __syncthreads();
    #pragma unroll
    for (int off = 128; off > 0; off >>= 1) {
        if (t < off) red[t] += red[t + off];
        __syncthreads();
    }
    if (t == 0) g_Z[b] = red[0];
}

// ============ kD: attn out + weighted atom-sum partials ============
__global__ void kD(const float* __restrict__ aq, const float* __restrict__ mask,
                   float* __restrict__ attn_out) {
    __shared__ float w[128];
    __shared__ float swred[4];
    int b = blockIdx.y;
    int c = blockIdx.x;
    int i0 = c * 128;
    int t = threadIdx.x;
    int lane = t & 31, warp = t >> 5;
    int i = i0 + t;
    float invZ = 1.0f / g_Z[b];
    float attn = g_agg[b * Nn + i] * invZ;
    if (attn_out) attn_out[b * Nn + i] = attn;
    float wv = mask[b * Nn + i] * attn;
    w[t] = wv;
    // reduce sum of w
    float sw = wv;
    #pragma unroll
    for (int off = 16; off > 0; off >>= 1) sw += __shfl_xor_sync(0xffffffffu, sw, off);
    if (lane == 0) swred[warp] = sw;
    __syncthreads();
    if (t == 0) g_swpart[b][c] = swred[0] + swred[1] + swred[2] + swred[3];
    // u partial
    const float* p = aq + ((size_t)(b * Nn + i0)) * Fn + t;
    float a0 = 0.f, a1 = 0.f, a2 = 0.f, a3 = 0.f;
    #pragma unroll 8
    for (int a = 0; a < 128; a += 4) {
        a0 = fmaf(w[a + 0], p[(a + 0) * Fn], a0);
        a1 = fmaf(w[a + 1], p[(a + 1) * Fn], a1);
        a2 = fmaf(w[a + 2], p[(a + 2) * Fn], a2);
        a3 = fmaf(w[a + 3], p[(a + 3) * Fn], a3);
    }
    g_upart[b][c][t] = (a0 + a1) + (a2 + a3);
}

// ============ kE: context = u @ Wv + sw * bv ============
__global__ void kE(const float* __restrict__ Wv, const float* __restrict__ bv,
                   float* __restrict__ ctx_out) {
    if (!ctx_out) return;
    __shared__ float su[Fn];
    int b = blockIdx.x;
    int d = threadIdx.x;
    float s = 0.f;
    #pragma unroll
    for (int c = 0; c < 8; c++) s += g_upart[b][c][d];
    su[d] = s;
    __syncthreads();
    float sw = 0.f;
    #pragma unroll
    for (int c = 0; c < 8; c++) sw += g_swpart[b][c];
    float c0 = sw * bv[d], c1 = 0.f, c2 = 0.f, c3 = 0.f;
    #pragma unroll 8
    for (int f = 0; f < Fn; f += 4) {
        c0 = fmaf(Wv[(f + 0) * Fn + d], su[f + 0], c0);
        c1 = fmaf(Wv[(f + 1) * Fn + d], su[f + 1], c1);
        c2 = fmaf(Wv[(f + 2) * Fn + d], su[f + 2], c2);
        c3 = fmaf(Wv[(f + 3) * Fn + d], su[f + 3], c3);
    }
    ctx_out[b * Dn + d] = (c0 + c1) + (c2 + c3);
}

// ---------------- host launch ----------------
extern "C" void kernel_launch(void* const* d_in, const int* in_sizes, int n_in,
                              void* d_out, int out_size) {
    const float* aq   = (const float*)d_in[0];
    const float* mask = (const float*)d_in[1];
    const float* Wq   = (const float*)d_in[2];
    const float* bq   = (const float*)d_in[3];
    const float* Wk   = (const float*)d_in[4];
    const float* bk   = (const float*)d_in[5];
    const float* Wv   = (const float*)d_in[6];
    const float* bv   = (const float*)d_in[7];

    float* out = (float*)d_out;
    float* attn_out = nullptr;
    float* ctx_out = nullptr;
    if (out_size >= Bn * Nn + Bn * Dn) { attn_out = out; ctx_out = out + Bn * Nn; }
    else if (out_size == Bn * Nn)      { attn_out = out; }
    else                               { ctx_out = out; }

    static bool attr_set = false;
    if (!attr_set) {
        cudaFuncSetAttribute(kB, cudaFuncAttributeMaxDynamicSharedMemorySize, KB_SMEM);
        attr_set = true;
    }

    kA<<<Fn + 1 + Bn * 8, 128>>>(aq, Wq, Wk, bq, bk);
    kB<<<dim3(16, Bn), 256, KB_SMEM>>>(aq, mask, Wq, Wk, bq, bk);
    kC<<<Bn, 256>>>(mask);
    kD<<<dim3(8, Bn), 128>>>(aq, mask, attn_out);
    kE<<<Bn, 128>>>(Wv, bv, ctx_out);
}

// round 3
// speedup vs baseline: 1.2646x; 1.0404x over previous
#include <cuda_runtime.h>
#include <math.h>

#define Bn 32
#define Nn 1024
#define Fn 128
#define Dn 128

// dk = (D^-0.5)/N = 1/(sqrt(128)*1024)
#define DKC 8.6316745750311e-05f

typedef unsigned long long ull;

// ---------------- scratch (device globals) ----------------
__device__ float g_M[Fn * Fn];            // M[f][g] = sum_d Wq[f,d]*Wk[g,d]
__device__ float g_u12[Fn];               // Wq bk + Wk bq
__device__ float g_c[1];                  // bq . bk
__device__ float g_Apart[Bn][16][Fn];     // partial column sums of aq
__device__ float g_agg[Bn * Nn];          // agg, then exp values (in-place)
__device__ float g_n2part[Bn][16];        // per-block partial sum of agg^2
__device__ float g_Zpart[Bn][8];          // softmax denominator partials
__device__ float g_upart[Bn][8][Fn];      // partial sum_i e_i aq_i

// ---------------- f32x2 helpers ----------------
__device__ __forceinline__ void ffma2(ull& d, ull a, ull b) {
    asm("fma.rn.f32x2 %0, %1, %2, %0;" : "+l"(d) : "l"(a), "l"(b));
}
__device__ __forceinline__ ull pk2(float lo, float hi) {
    ull r; asm("mov.b64 %0, {%1,%2};" : "=l"(r) : "f"(lo), "f"(hi)); return r;
}
__device__ __forceinline__ void upk2(ull v, float& lo, float& hi) {
    asm("mov.b64 {%0,%1}, %2;" : "=f"(lo), "=f"(hi) : "l"(v));
}

// ============ kA: precompute (M, u12, c) + column-sum partials, 256-thr blocks ============
__global__ void __launch_bounds__(256) kA(const float* __restrict__ aq,
                   const float* __restrict__ Wq, const float* __restrict__ Wk,
                   const float* __restrict__ bq, const float* __restrict__ bk) {
    int blk = blockIdx.x;
    int t = threadIdx.x;
    if (blk < 64) {
        // two M rows per block: rows 2*blk, 2*blk+1
        __shared__ float srow[256];
        srow[t] = Wq[blk * 256 + t];
        __syncthreads();
        int row = t >> 7;          // 0/1
        int c = t & 127;
        const float* wk = Wk + c * Fn;
        const float* sr = srow + row * 128;
        float a0 = 0.f, a1 = 0.f, a2 = 0.f, a3 = 0.f;
        #pragma unroll 8
        for (int d = 0; d < Fn; d += 4) {
            a0 = fmaf(sr[d + 0], wk[d + 0], a0);
            a1 = fmaf(sr[d + 1], wk[d + 1], a1);
            a2 = fmaf(sr[d + 2], wk[d + 2], a2);
            a3 = fmaf(sr[d + 3], wk[d + 3], a3);
        }
        g_M[(2 * blk + row) * Fn + c] = (a0 + a1) + (a2 + a3);
    } else if (blk == 64) {
        __shared__ float sbq[Fn], sbk[Fn];
        if (t < 128) { sbq[t] = bq[t]; sbk[t] = bk[t]; }
        __syncthreads();
        if (t < 128) {
            float a0 = 0.f, a1 = 0.f;
            #pragma unroll 8
            for (int d = 0; d < Fn; d += 2) {
                a0 = fmaf(Wq[t * Fn + d], sbk[d], a0);
                a0 = fmaf(Wk[t * Fn + d], sbq[d], a0);
                a1 = fmaf(Wq[t * Fn + d + 1], sbk[d + 1], a1);
                a1 = fmaf(Wk[t * Fn + d + 1], sbq[d + 1], a1);
            }
            g_u12[t] = a0 + a1;
            if (t == 0) {
                float c = 0.f;
                for (int d = 0; d < Fn; d++) c = fmaf(sbq[d], sbk[d], c);
                g_c[0] = c;
            }
        }
    } else {
        // column-sum partial: 64 rows of batch b, float4 per thread
        __shared__ float sred[8 * 128];
        int m = blk - 65;
        int b = m >> 4, ch = m & 15;
        int fq = (t & 31) * 4;
        int rg = t >> 5;                 // 8 row-groups x 8 rows
        const float* p = aq + ((size_t)(b * Nn + ch * 64 + rg * 8)) * Fn + fq;
        float4 s0 = {0, 0, 0, 0}, s1 = {0, 0, 0, 0};
        #pragma unroll
        for (int r = 0; r < 8; r += 2) {
            float4 v0 = *reinterpret_cast<const float4*>(p + (r + 0) * Fn);
            float4 v1 = *reinterpret_cast<const float4*>(p + (r + 1) * Fn);
            s0.x += v0.x; s0.y += v0.y; s0.z += v0.z; s0.w += v0.w;
            s1.x += v1.x; s1.y += v1.y; s1.z += v1.z; s1.w += v1.w;
        }
        sred[rg * 128 + fq + 0] = s0.x + s1.x;
        sred[rg * 128 + fq + 1] = s0.y + s1.y;
        sred[rg * 128 + fq + 2] = s0.z + s1.z;
        sred[rg * 128 + fq + 3] = s0.w + s1.w;
        __syncthreads();
        if (t < 128) {
            float s = 0.f;
            #pragma unroll
            for (int g = 0; g < 8; g++) s += sred[g * 128 + t];
            g_Apart[b][ch][t] = s;
        }
    }
}

// ============ kB: dominant kernel — per-atom agg via packed FFMA2 ============
#define STM 129                         // M row stride (conflict-free)
#define STX 66                          // transposed X stride
#define KB_SMEM ((Fn * STM + Fn * STX + 3 * Fn) * 4)

__global__ void __launch_bounds__(256, 2) kB(const float* __restrict__ aq,
                                             const float* __restrict__ mask,
                                             const float* __restrict__ Wq,
                                             const float* __restrict__ Wk,
                                             const float* __restrict__ bq,
                                             const float* __restrict__ bk) {
    extern __shared__ float sm[];
    float* sM  = sm;                     // [128][129]
    float* sXT = sM + Fn * STM;          // [128 f][66]
    float* sA  = sXT + Fn * STX;         // [128]
    float* sS  = sA + Fn;                // [128]
    float* sWc = sS + Fn;                // [128]
    __shared__ float sred[8];

    const int b = blockIdx.y;
    const int atom0 = blockIdx.x * 64;
    const int t = threadIdx.x;
    const int warp = t >> 5, lane = t & 31;
    const int r0 = warp * 8;

    for (int idx = t; idx < Fn * Fn; idx += 256)
        sM[(idx >> 7) * STM + (idx & 127)] = g_M[idx];
    const float* aqb = aq + ((size_t)(b * Nn + atom0)) * Fn;
    for (int idx = t; idx < 64 * Fn; idx += 256)
        sXT[(idx & 127) * STX + (idx >> 7)] = aqb[idx];

    if (t < Fn) {
        float s = 0.f;
        #pragma unroll
        for (int c = 0; c < 16; c++) s += g_Apart[b][c][t];
        sA[t] = s;
    }
    __syncthreads();

    if (t < Fn) {
        float s0 = 1024.0f * bk[t], s1 = 0.f, s2 = 0.f, s3 = 0.f;
        #pragma unroll 8
        for (int f = 0; f < Fn; f += 4) {
            s0 = fmaf(Wk[(f + 0) * Fn + t], sA[f + 0], s0);
            s1 = fmaf(Wk[(f + 1) * Fn + t], sA[f + 1], s1);
            s2 = fmaf(Wk[(f + 2) * Fn + t], sA[f + 2], s2);
            s3 = fmaf(Wk[(f + 3) * Fn + t], sA[f + 3], s3);
        }
        sS[t] = (s0 + s1) + (s2 + s3);
    }
    __syncthreads();

    float cc_part = 0.f;
    if (t < Fn) {
        float w0 = -g_u12[t], w1 = 0.f, w2 = 0.f, w3 = 0.f;
        const float* wq = Wq + t * Fn;
        #pragma unroll 8
        for (int d = 0; d < Fn; d += 4) {
            w0 = fmaf(wq[d + 0], sS[d + 0], w0);
            w1 = fmaf(wq[d + 1], sS[d + 1], w1);
            w2 = fmaf(wq[d + 2], sS[d + 2], w2);
            w3 = fmaf(wq[d + 3], sS[d + 3], w3);
        }
        sWc[t] = (w0 + w1) + (w2 + w3);
        cc_part = bq[t] * sS[t];
    }
    #pragma unroll
    for (int off = 16; off > 0; off >>= 1)
        cc_part += __shfl_xor_sync(0xffffffffu, cc_part, off);
    if (lane == 0) sred[warp] = cc_part;
    __syncthreads();
    const float ccomb = (sred[0] + sred[1] + sred[2] + sred[3]) - g_c[0];
    __syncthreads();

    ull acc[4][4];
    #pragma unroll
    for (int k = 0; k < 4; k++)
        #pragma unroll
        for (int a2 = 0; a2 < 4; a2++) acc[k][a2] = 0ull;

    #pragma unroll 4
    for (int g = 0; g < Fn; g++) {
        const float* xp = &sXT[g * STX + r0];
        ull x0 = *reinterpret_cast<const ull*>(xp + 0);
        ull x1 = *reinterpret_cast<const ull*>(xp + 2);
        ull x2 = *reinterpret_cast<const ull*>(xp + 4);
        ull x3 = *reinterpret_cast<const ull*>(xp + 6);
        #pragma unroll
        for (int k = 0; k < 4; k++) {
            float m = sM[(lane + 32 * k) * STM + g];
            ull mm = pk2(m, m);
            ffma2(acc[k][0], mm, x0);
            ffma2(acc[k][1], mm, x1);
            ffma2(acc[k][2], mm, x2);
            ffma2(acc[k][3], mm, x3);
        }
    }

    float wc[4];
    #pragma unroll
    for (int k = 0; k < 4; k++) wc[k] = sWc[lane + 32 * k];

    float n2local = 0.f;
    #pragma unroll
    for (int a2 = 0; a2 < 4; a2++) {
        float ylo[4], yhi[4];
        #pragma unroll
        for (int k = 0; k < 4; k++) upk2(acc[k][a2], ylo[k], yhi[k]);
        #pragma unroll
        for (int half = 0; half < 2; half++) {
            int a = 2 * a2 + half;
            float p1 = 0.f, p2 = 0.f;
            #pragma unroll
            for (int k = 0; k < 4; k++) {
                float xf = sXT[(lane + 32 * k) * STX + r0 + a];
                p1 = fmaf(xf, half ? yhi[k] : ylo[k], p1);
                p2 = fmaf(xf, wc[k], p2);
            }
            #pragma unroll
            for (int off = 16; off > 0; off >>= 1) {
                p1 += __shfl_xor_sync(0xffffffffu, p1, off);
                p2 += __shfl_xor_sync(0xffffffffu, p2, off);
            }
            if (lane == 0) {
                int i = atom0 + r0 + a;
                float mv = mask[b * Nn + i];
                float aggv = mv * DKC * (p2 + ccomb - p1);
                g_agg[b * Nn + i] = aggv;
                n2local = fmaf(aggv, aggv, n2local);
            }
        }
    }
    if (lane == 0) sred[warp] = n2local;
    __syncthreads();
    if (t == 0) {
        float s = 0.f;
        #pragma unroll
        for (int w = 0; w < 8; w++) s += sred[w];
        g_n2part[b][blockIdx.x] = s;
    }
}

// ============ kC: fused normalize+exp+Z partial + weighted colsum partial ============
// grid (8, Bn), 256 threads; chunk = 128 atoms.
__global__ void __launch_bounds__(256) kC(const float* __restrict__ aq,
                                          const float* __restrict__ mask) {
    __shared__ float w[128];
    __shared__ float sred[8 * 128];
    __shared__ float zred[4];
    int b = blockIdx.y, ch = blockIdx.x;
    int t = threadIdx.x, lane = t & 31, warp = t >> 5;
    int i0 = ch * 128;

    float n2 = 0.f;
    #pragma unroll
    for (int j = 0; j < 16; j++) n2 += g_n2part[b][j];
    float invn = rsqrtf(n2);

    float e = 0.f;
    if (t < 128) {
        int i = b * Nn + i0 + t;
        float a = g_agg[i];
        float mv = mask[i];
        e = (mv != 0.f) ? __expf(a * invn) : 0.f;  // masked -> -1e9 -> exp 0
        g_agg[i] = e;
        w[t] = e;                                   // weight == e (binary mask)
    }
    float ze = e;
    #pragma unroll
    for (int off = 16; off > 0; off >>= 1) ze += __shfl_xor_sync(0xffffffffu, ze, off);
    if (lane == 0 && warp < 4) zred[warp] = ze;
    __syncthreads();                                // also publishes w[]
    if (t == 0) g_Zpart[b][ch] = zred[0] + zred[1] + zred[2] + zred[3];

    // weighted colsum: u'[f] = sum_r w[r] * aq[b, i0+r, f]
    int fq = (t & 31) * 4;
    int rg = t >> 5;                                // 8 groups x 16 rows
    const float* p = aq + ((size_t)(b * Nn + i0 + rg * 16)) * Fn + fq;
    const float* wp = w + rg * 16;
    float4 s0 = {0, 0, 0, 0}, s1 = {0, 0, 0, 0};
    #pragma unroll
    for (int r = 0; r < 16; r += 2) {
        float w0 = wp[r], w1 = wp[r + 1];
        float4 v0 = *reinterpret_cast<const float4*>(p + (r + 0) * Fn);
        float4 v1 = *reinterpret_cast<const float4*>(p + (r + 1) * Fn);
        s0.x = fmaf(w0, v0.x, s0.x); s0.y = fmaf(w0, v0.y, s0.y);
        s0.z = fmaf(w0, v0.z, s0.z); s0.w = fmaf(w0, v0.w, s0.w);
        s1.x = fmaf(w1, v1.x, s1.x); s1.y = fmaf(w1, v1.y, s1.y);
        s1.z = fmaf(w1, v1.z, s1.z); s1.w = fmaf(w1, v1.w, s1.w);
    }
    sred[rg * 128 + fq + 0] = s0.x + s1.x;
    sred[rg * 128 + fq + 1] = s0.y + s1.y;
    sred[rg * 128 + fq + 2] = s0.z + s1.z;
    sred[rg * 128 + fq + 3] = s0.w + s1.w;
    __syncthreads();
    if (t < 128) {
        float s = 0.f;
        #pragma unroll
        for (int g = 0; g < 8; g++) s += sred[g * 128 + t];
        g_upart[b][ch][t] = s;
    }
}

// ============ kE: Z reduce, attn out, context = (u'.Wv)/Z + bv ============
__global__ void __launch_bounds__(256) kE(const float* __restrict__ Wv,
                                          const float* __restrict__ bv,
                                          float* __restrict__ attn_out,
                                          float* __restrict__ ctx_out) {
    __shared__ float su[Fn];
    int b = blockIdx.x, t = threadIdx.x;
    float Z = 0.f;
    #pragma unroll
    for (int c = 0; c < 8; c++) Z += g_Zpart[b][c];
    float invZ = 1.0f / Z;
    if (t < 128) {
        float s = 0.f;
        #pragma unroll
        for (int c = 0; c < 8; c++) s += g_upart[b][c][t];
        su[t] = s;
    }
    __syncthreads();
    if (attn_out) {
        #pragma unroll
        for (int j = 0; j < 4; j++) {
            int i = b * Nn + j * 256 + t;
            attn_out[i] = g_agg[i] * invZ;
        }
    }
    if (ctx_out && t < 128) {
        float c0 = 0.f, c1 = 0.f, c2 = 0.f, c3 = 0.f;
        #pragma unroll 8
        for (int f = 0; f < Fn; f += 4) {
            c0 = fmaf(Wv[(f + 0) * Fn + t], su[f + 0], c0);
            c1 = fmaf(Wv[(f + 1) * Fn + t], su[f + 1], c1);
            c2 = fmaf(Wv[(f + 2) * Fn + t], su[f + 2], c2);
            c3 = fmaf(Wv[(f + 3) * Fn + t], su[f + 3], c3);
        }
        ctx_out[b * Dn + t] = ((c0 + c1) + (c2 + c3)) * invZ + bv[t];
    }
}

// ---------------- host launch ----------------
extern "C" void kernel_launch(void* const* d_in, const int* in_sizes, int n_in,
                              void* d_out, int out_size) {
    const float* aq   = (const float*)d_in[0];
    const float* mask = (const float*)d_in[1];
    const float* Wq   = (const float*)d_in[2];
    const float* bq   = (const float*)d_in[3];
    const float* Wk   = (const float*)d_in[4];
    const float* bk   = (const float*)d_in[5];
    const float* Wv   = (const float*)d_in[6];
    const float* bv   = (const float*)d_in[7];

    float* out = (float*)d_out;
    float* attn_out = nullptr;
    float* ctx_out = nullptr;
    if (out_size >= Bn * Nn + Bn * Dn) { attn_out = out; ctx_out = out + Bn * Nn; }
    else if (out_size == Bn * Nn)      { attn_out = out; }
    else                               { ctx_out = out; }

    cudaFuncSetAttribute(kB, cudaFuncAttributeMaxDynamicSharedMemorySize, KB_SMEM);

    kA<<<65 + Bn * 16, 256>>>(aq, Wq, Wk, bq, bk);
    kB<<<dim3(16, Bn), 256, KB_SMEM>>>(aq, mask, Wq, Wk, bq, bk);
    kC<<<dim3(8, Bn), 256>>>(aq, mask);
    kE<<<Bn, 256>>>(Wv, bv, attn_out, ctx_out);
}

// round 4
// speedup vs baseline: 1.9115x; 1.5115x over previous
#include <cuda_runtime.h>
#include <math.h>

#define Bn 32
#define Nn 1024
#define Fn 128
#define Dn 128

// dk = (D^-0.5)/N = 1/(sqrt(128)*1024)
#define DKC 8.6316745750311e-05f

typedef unsigned long long ull;

// ---------------- scratch (device globals) ----------------
__device__ float g_M[Fn * Fn];            // M[f][g] = sum_d Wq[f,d]*Wk[g,d]
__device__ float g_Apart[Bn][16][Fn];     // partial column sums of aq
__device__ float g_wcomb[Bn][Fn];         // Wq S - u12 per batch
__device__ float g_ccomb[Bn];             // bq.S - bq.bk per batch
__device__ float g_agg[Bn * Nn];          // agg, then exp values (in-place)
__device__ float g_n2part[Bn][16];        // per-block partial sum of agg^2
__device__ float g_Zpart[Bn][8];          // softmax denominator partials
__device__ float g_upart[Bn][8][Fn];      // partial sum_i e_i aq_i
__device__ int   g_cntA[Bn];              // arrival counters (reset by consumer)
__device__ int   g_cntC[Bn];

// ---------------- f32x2 helpers ----------------
__device__ __forceinline__ void ffma2(ull& d, ull a, ull b) {
    asm("fma.rn.f32x2 %0, %1, %2, %0;" : "+l"(d) : "l"(a), "l"(b));
}
__device__ __forceinline__ ull pk2(float lo, float hi) {
    ull r; asm("mov.b64 %0, {%1,%2};" : "=l"(r) : "f"(lo), "f"(hi)); return r;
}
__device__ __forceinline__ void upk2(ull v, float& lo, float& hi) {
    asm("mov.b64 {%0,%1}, %2;" : "=f"(lo), "=f"(hi) : "l"(v));
}

// ============ kA: M precompute + colsum partials + per-batch S/wcomb tail ============
__global__ void __launch_bounds__(256) kA(const float* __restrict__ aq,
                   const float* __restrict__ Wq, const float* __restrict__ Wk,
                   const float* __restrict__ bq, const float* __restrict__ bk) {
    __shared__ float sred[8 * 128];
    __shared__ float srow[256];
    __shared__ float sA[128], sT[128], sbq[128];
    __shared__ float credw[4];
    __shared__ int isLast;

    int blk = blockIdx.x;
    int t = threadIdx.x;
    int lane = t & 31, warp = t >> 5;

    if (blk < 64) {
        // ---- two M rows per block ----
        srow[t] = Wq[blk * 256 + t];
        __syncthreads();
        int row = t >> 7;
        int c = t & 127;
        const float* sr = srow + row * 128;
        const float4* wk4 = reinterpret_cast<const float4*>(Wk + c * Fn);
        float a0 = 0.f, a1 = 0.f, a2 = 0.f, a3 = 0.f;
        #pragma unroll
        for (int q = 0; q < 32; q += 4) {
            float4 v0 = wk4[q + 0], v1 = wk4[q + 1], v2 = wk4[q + 2], v3 = wk4[q + 3];
            a0 = fmaf(sr[4*q + 0], v0.x, a0); a0 = fmaf(sr[4*q + 1], v0.y, a0);
            a0 = fmaf(sr[4*q + 2], v0.z, a0); a0 = fmaf(sr[4*q + 3], v0.w, a0);
            a1 = fmaf(sr[4*q + 4], v1.x, a1); a1 = fmaf(sr[4*q + 5], v1.y, a1);
            a1 = fmaf(sr[4*q + 6], v1.z, a1); a1 = fmaf(sr[4*q + 7], v1.w, a1);
            a2 = fmaf(sr[4*q + 8], v2.x, a2); a2 = fmaf(sr[4*q + 9], v2.y, a2);
            a2 = fmaf(sr[4*q +10], v2.z, a2); a2 = fmaf(sr[4*q +11], v2.w, a2);
            a3 = fmaf(sr[4*q +12], v3.x, a3); a3 = fmaf(sr[4*q +13], v3.y, a3);
            a3 = fmaf(sr[4*q +14], v3.z, a3); a3 = fmaf(sr[4*q +15], v3.w, a3);
        }
        g_M[(2 * blk + row) * Fn + c] = (a0 + a1) + (a2 + a3);
        return;
    }

    // ---- colsum partial: 64 rows of batch b ----
    int m = blk - 64;
    int b = m >> 4, ch = m & 15;
    {
        int fq = (t & 31) * 4;
        int rg = t >> 5;
        const float* p = aq + ((size_t)(b * Nn + ch * 64 + rg * 8)) * Fn + fq;
        float4 s0 = {0, 0, 0, 0}, s1 = {0, 0, 0, 0};
        #pragma unroll
        for (int r = 0; r < 8; r += 2) {
            float4 v0 = *reinterpret_cast<const float4*>(p + (r + 0) * Fn);
            float4 v1 = *reinterpret_cast<const float4*>(p + (r + 1) * Fn);
            s0.x += v0.x; s0.y += v0.y; s0.z += v0.z; s0.w += v0.w;
            s1.x += v1.x; s1.y += v1.y; s1.z += v1.z; s1.w += v1.w;
        }
        sred[rg * 128 + fq + 0] = s0.x + s1.x;
        sred[rg * 128 + fq + 1] = s0.y + s1.y;
        sred[rg * 128 + fq + 2] = s0.z + s1.z;
        sred[rg * 128 + fq + 3] = s0.w + s1.w;
        __syncthreads();
        if (t < 128) {
            float s = 0.f;
            #pragma unroll
            for (int g = 0; g < 8; g++) s += sred[g * 128 + t];
            g_Apart[b][ch][t] = s;
        }
    }

    // ---- arrival; 16th block computes S, wcomb, ccomb for batch b ----
    __threadfence();
    __syncthreads();
    if (t == 0) {
        int r = atomicAdd(&g_cntA[b], 1);
        isLast = (r == 15);
    }
    __syncthreads();
    if (!isLast) return;
    __threadfence();

    if (t < 128) {
        float s = 0.f;
        #pragma unroll
        for (int c = 0; c < 16; c++) s += g_Apart[b][c][t];
        sA[t] = s;
        sbq[t] = bq[t];
    }
    __syncthreads();
    if (t < 128) {
        // S[d] = sum_f Wk[f,d]*A[f] + N*bk[d];  T = S - bk
        float s0 = 0.f, s1 = 0.f, s2 = 0.f, s3 = 0.f;
        #pragma unroll 8
        for (int f = 0; f < Fn; f += 4) {
            s0 = fmaf(Wk[(f + 0) * Fn + t], sA[f + 0], s0);
            s1 = fmaf(Wk[(f + 1) * Fn + t], sA[f + 1], s1);
            s2 = fmaf(Wk[(f + 2) * Fn + t], sA[f + 2], s2);
            s3 = fmaf(Wk[(f + 3) * Fn + t], sA[f + 3], s3);
        }
        sT[t] = (s0 + s1) + (s2 + s3) + 1023.0f * bk[t];   // S - bk = (..) + (N-1)*bk
    }
    __syncthreads();
    float cc = 0.f;
    if (t < 128) {
        // wcomb[t] = sum_d Wq[t,d]*T[d] - sum_d Wk[t,d]*bq[d]
        const float4* wq4 = reinterpret_cast<const float4*>(Wq + t * Fn);
        const float4* wk4 = reinterpret_cast<const float4*>(Wk + t * Fn);
        float w0 = 0.f, w1 = 0.f, w2 = 0.f, w3 = 0.f;
        #pragma unroll 8
        for (int q = 0; q < 32; q += 2) {
            float4 a = wq4[q], b4 = wk4[q], c4 = wq4[q + 1], d4 = wk4[q + 1];
            int d0 = 4 * q, d1 = 4 * q + 4;
            w0 = fmaf(a.x, sT[d0 + 0], w0);  w1 = fmaf(-b4.x, sbq[d0 + 0], w1);
            w0 = fmaf(a.y, sT[d0 + 1], w0);  w1 = fmaf(-b4.y, sbq[d0 + 1], w1);
            w0 = fmaf(a.z, sT[d0 + 2], w0);  w1 = fmaf(-b4.z, sbq[d0 + 2], w1);
            w0 = fmaf(a.w, sT[d0 + 3], w0);  w1 = fmaf(-b4.w, sbq[d0 + 3], w1);
            w2 = fmaf(c4.x, sT[d1 + 0], w2); w3 = fmaf(-d4.x, sbq[d1 + 0], w3);
            w2 = fmaf(c4.y, sT[d1 + 1], w2); w3 = fmaf(-d4.y, sbq[d1 + 1], w3);
            w2 = fmaf(c4.z, sT[d1 + 2], w2); w3 = fmaf(-d4.z, sbq[d1 + 2], w3);
            w2 = fmaf(c4.w, sT[d1 + 3], w2); w3 = fmaf(-d4.w, sbq[d1 + 3], w3);
        }
        g_wcomb[b][t] = (w0 + w1) + (w2 + w3);
        cc = sbq[t] * sT[t];
    }
    #pragma unroll
    for (int off = 16; off > 0; off >>= 1)
        cc += __shfl_xor_sync(0xffffffffu, cc, off);
    if (lane == 0 && warp < 4) credw[warp] = cc;
    __syncthreads();
    if (t == 0) {
        g_ccomb[b] = credw[0] + credw[1] + credw[2] + credw[3];
        g_cntA[b] = 0;   // reset for next graph replay
    }
}

// ============ kB: dominant kernel — per-atom agg via packed FFMA2 ============
#define STM 129
#define STX 66
#define KB_SMEM ((Fn * STM + Fn * STX + Fn) * 4)

__global__ void __launch_bounds__(256, 2) kB(const float* __restrict__ aq,
                                             const float* __restrict__ mask) {
    extern __shared__ float sm[];
    float* sM  = sm;                     // [128][129]
    float* sXT = sM + Fn * STM;          // [128 f][66]
    float* sWc = sXT + Fn * STX;         // [128]
    __shared__ float sred[8];

    const int b = blockIdx.y;
    const int atom0 = blockIdx.x * 64;
    const int t = threadIdx.x;
    const int warp = t >> 5, lane = t & 31;
    const int r0 = warp * 8;

    for (int idx = t; idx < Fn * Fn; idx += 256)
        sM[(idx >> 7) * STM + (idx & 127)] = g_M[idx];
    const float* aqb = aq + ((size_t)(b * Nn + atom0)) * Fn;
    for (int idx = t; idx < 64 * Fn; idx += 256)
        sXT[(idx & 127) * STX + (idx >> 7)] = aqb[idx];
    if (t < 128) sWc[t] = g_wcomb[b][t];
    const float ccomb = g_ccomb[b];
    __syncthreads();

    ull acc[4][4];
    #pragma unroll
    for (int k = 0; k < 4; k++)
        #pragma unroll
        for (int a2 = 0; a2 < 4; a2++) acc[k][a2] = 0ull;

    #pragma unroll 4
    for (int g = 0; g < Fn; g++) {
        const float* xp = &sXT[g * STX + r0];
        ull x0 = *reinterpret_cast<const ull*>(xp + 0);
        ull x1 = *reinterpret_cast<const ull*>(xp + 2);
        ull x2 = *reinterpret_cast<const ull*>(xp + 4);
        ull x3 = *reinterpret_cast<const ull*>(xp + 6);
        #pragma unroll
        for (int k = 0; k < 4; k++) {
            float m = sM[(lane + 32 * k) * STM + g];
            ull mm = pk2(m, m);
            ffma2(acc[k][0], mm, x0);
            ffma2(acc[k][1], mm, x1);
            ffma2(acc[k][2], mm, x2);
            ffma2(acc[k][3], mm, x3);
        }
    }

    float wc[4];
    #pragma unroll
    for (int k = 0; k < 4; k++) wc[k] = sWc[lane + 32 * k];

    float n2local = 0.f;
    #pragma unroll
    for (int a2 = 0; a2 < 4; a2++) {
        float ylo[4], yhi[4];
        #pragma unroll
        for (int k = 0; k < 4; k++) upk2(acc[k][a2], ylo[k], yhi[k]);
        #pragma unroll
        for (int half = 0; half < 2; half++) {
            int a = 2 * a2 + half;
            float p1 = 0.f, p2 = 0.f;
            #pragma unroll
            for (int k = 0; k < 4; k++) {
                float xf = sXT[(lane + 32 * k) * STX + r0 + a];
                p1 = fmaf(xf, half ? yhi[k] : ylo[k], p1);
                p2 = fmaf(xf, wc[k], p2);
            }
            #pragma unroll
            for (int off = 16; off > 0; off >>= 1) {
                p1 += __shfl_xor_sync(0xffffffffu, p1, off);
                p2 += __shfl_xor_sync(0xffffffffu, p2, off);
            }
            if (lane == 0) {
                int i = atom0 + r0 + a;
                float mv = mask[b * Nn + i];
                float aggv = mv * DKC * (p2 + ccomb - p1);
                g_agg[b * Nn + i] = aggv;
                n2local = fmaf(aggv, aggv, n2local);
            }
        }
    }
    if (lane == 0) sred[warp] = n2local;
    __syncthreads();
    if (t == 0) {
        float s = 0.f;
        #pragma unroll
        for (int w = 0; w < 8; w++) s += sred[w];
        g_n2part[b][blockIdx.x] = s;
    }
}

// ============ kC: exp/Z/weighted-colsum + last-block-per-batch finalize ============
__global__ void __launch_bounds__(256) kC(const float* __restrict__ aq,
                                          const float* __restrict__ mask,
                                          const float* __restrict__ Wv,
                                          const float* __restrict__ bv,
                                          float* __restrict__ attn_out,
                                          float* __restrict__ ctx_out) {
    __shared__ float w[128];
    __shared__ float sred[8 * 128];
    __shared__ float zred[4];
    __shared__ int isLast;
    int b = blockIdx.y, ch = blockIdx.x;
    int t = threadIdx.x, lane = t & 31, warp = t >> 5;
    int i0 = ch * 128;

    float n2 = 0.f;
    #pragma unroll
    for (int j = 0; j < 16; j++) n2 += g_n2part[b][j];
    float invn = rsqrtf(n2);

    float e = 0.f;
    if (t < 128) {
        int i = b * Nn + i0 + t;
        float a = g_agg[i];
        float mv = mask[i];
        e = (mv != 0.f) ? __expf(a * invn) : 0.f;
        g_agg[i] = e;
        w[t] = e;
    }
    float ze = e;
    #pragma unroll
    for (int off = 16; off > 0; off >>= 1) ze += __shfl_xor_sync(0xffffffffu, ze, off);
    if (lane == 0 && warp < 4) zred[warp] = ze;
    __syncthreads();
    if (t == 0) g_Zpart[b][ch] = zred[0] + zred[1] + zred[2] + zred[3];

    // weighted colsum partial
    {
        int fq = (t & 31) * 4;
        int rg = t >> 5;
        const float* p = aq + ((size_t)(b * Nn + i0 + rg * 16)) * Fn + fq;
        const float* wp = w + rg * 16;
        float4 s0 = {0, 0, 0, 0}, s1 = {0, 0, 0, 0};
        #pragma unroll
        for (int r = 0; r < 16; r += 2) {
            float w0 = wp[r], w1 = wp[r + 1];
            float4 v0 = *reinterpret_cast<const float4*>(p + (r + 0) * Fn);
            float4 v1 = *reinterpret_cast<const float4*>(p + (r + 1) * Fn);
            s0.x = fmaf(w0, v0.x, s0.x); s0.y = fmaf(w0, v0.y, s0.y);
            s0.z = fmaf(w0, v0.z, s0.z); s0.w = fmaf(w0, v0.w, s0.w);
            s1.x = fmaf(w1, v1.x, s1.x); s1.y = fmaf(w1, v1.y, s1.y);
            s1.z = fmaf(w1, v1.z, s1.z); s1.w = fmaf(w1, v1.w, s1.w);
        }
        sred[rg * 128 + fq + 0] = s0.x + s1.x;
        sred[rg * 128 + fq + 1] = s0.y + s1.y;
        sred[rg * 128 + fq + 2] = s0.z + s1.z;
        sred[rg * 128 + fq + 3] = s0.w + s1.w;
        __syncthreads();
        if (t < 128) {
            float s = 0.f;
            #pragma unroll
            for (int g = 0; g < 8; g++) s += sred[g * 128 + t];
            g_upart[b][ch][t] = s;
        }
    }

    // ---- arrival; 8th block finalizes batch b ----
    __threadfence();
    __syncthreads();
    if (t == 0) {
        int r = atomicAdd(&g_cntC[b], 1);
        isLast = (r == 7);
    }
    __syncthreads();
    if (!isLast) return;
    __threadfence();

    float Z = 0.f;
    #pragma unroll
    for (int c = 0; c < 8; c++) Z += g_Zpart[b][c];
    float invZ = 1.0f / Z;

    if (attn_out) {
        #pragma unroll
        for (int j = 0; j < 4; j++) {
            int i = b * Nn + j * 256 + t;
            attn_out[i] = g_agg[i] * invZ;
        }
    }

    // su (reuse sred[0..127]); context split over two f-halves
    __syncthreads();
    float* sU = sred;
    float* spart = sred + 128;
    if (t < 128) {
        float s = 0.f;
        #pragma unroll
        for (int c = 0; c < 8; c++) s += g_upart[b][c][t];
        sU[t] = s;
    }
    __syncthreads();
    if (ctx_out) {
        int g = t >> 7, d = t & 127;
        int f0 = g * 64;
        float c0 = 0.f, c1 = 0.f, c2 = 0.f, c3 = 0.f;
        #pragma unroll 4
        for (int f = f0; f < f0 + 64; f += 4) {
            c0 = fmaf(Wv[(f + 0) * Fn + d], sU[f + 0], c0);
            c1 = fmaf(Wv[(f + 1) * Fn + d], sU[f + 1], c1);
            c2 = fmaf(Wv[(f + 2) * Fn + d], sU[f + 2], c2);
            c3 = fmaf(Wv[(f + 3) * Fn + d], sU[f + 3], c3);
        }
        spart[t] = (c0 + c1) + (c2 + c3);
        __syncthreads();
        if (t < 128)
            ctx_out[b * Dn + t] = (spart[t] + spart[t + 128]) * invZ + bv[t];
    }
    if (t == 0) g_cntC[b] = 0;   // reset for next replay
}

// ---------------- host launch ----------------
extern "C" void kernel_launch(void* const* d_in, const int* in_sizes, int n_in,
                              void* d_out, int out_size) {
    const float* aq   = (const float*)d_in[0];
    const float* mask = (const float*)d_in[1];
    const float* Wq   = (const float*)d_in[2];
    const float* bq   = (const float*)d_in[3];
    const float* Wk   = (const float*)d_in[4];
    const float* bk   = (const float*)d_in[5];
    const float* Wv   = (const float*)d_in[6];
    const float* bv   = (const float*)d_in[7];

    float* out = (float*)d_out;
    float* attn_out = nullptr;
    float* ctx_out = nullptr;
    if (out_size >= Bn * Nn + Bn * Dn) { attn_out = out; ctx_out = out + Bn * Nn; }
    else if (out_size == Bn * Nn)      { attn_out = out; }
    else                               { ctx_out = out; }

    cudaFuncSetAttribute(kB, cudaFuncAttributeMaxDynamicSharedMemorySize, KB_SMEM);

    kA<<<64 + Bn * 16, 256>>>(aq, Wq, Wk, bq, bk);
    kB<<<dim3(16, Bn), 256, KB_SMEM>>>(aq, mask);
    kC<<<dim3(8, Bn), 256>>>(aq, mask, Wv, bv, attn_out, ctx_out);
}